// round 7
// baseline (speedup 1.0000x reference)
#include <cuda_runtime.h>
#include <cuda_bf16.h>
#include <cstdint>

#define D 128
#define MAXNZ 256          // row degree ~Poisson(32); max over 10k rows << 256
#define BM 16              // E-rows per GEMM CTA
#define SWS 132            // sW float stride -> conflict-free LDS.128 across d
#define MAXB 4096
#define MAXN 10240         // max rows of E / E'

__device__ float g_Ep[(size_t)MAXN * D];        // E' = E @ W^T
__device__ int   g_idx[(size_t)MAXB * MAXNZ];   // compacted nonzero indices
__device__ float g_wv [(size_t)MAXB * MAXNZ];   // compacted nonzero weights
__device__ int   g_cnt[MAXB];

// ---------------------------------------------------------------------------
// Kernel A (block-specialized):
//   GEMM CTAs (bid%4==2, bid/4<nGemm): E'[r][d] = sum_k E[r][k]*W[d][k]
//     for 16 rows r — W staged once in smem (stride-132, conflict-free),
//     R=2 register tile, all-float4 loop.
//   Scan CTAs (everything else): scan F[ids[sid]], compact nonzeros to
//     global lists. Pure DRAM work; GEMM hides in its shadow.
// ---------------------------------------------------------------------------
__global__ __launch_bounds__(256) void scan_gemm_kernel(
    const int*   __restrict__ ids,
    const float* __restrict__ F,
    const float* __restrict__ E,
    const float* __restrict__ W,
    int n_total, int nrows, int B, int nGemm)
{
    extern __shared__ __align__(16) float smem[];
    const int tid = threadIdx.x;
    const int bid = blockIdx.x;

    if (((bid & 3) == 2) && ((bid >> 2) < nGemm)) {
        // ---------------- GEMM CTA ----------------
        float* sW = smem;                 // [128][SWS]
        float* sA = smem + D * SWS;       // [BM][128]
        const int gid  = bid >> 2;
        const int row0 = gid * BM;
        const int tx   = tid & 31;
        const int ty   = tid >> 5;

        {
            const float4* __restrict__ W4 = (const float4*)W;
            float4* __restrict__ sW4 = (float4*)sW;
#pragma unroll
            for (int t = 0; t < 16; ++t) {
                const int i4 = tid + t * 256;
                const int dd = i4 >> 5;
                const int c  = i4 & 31;
                sW4[dd * (SWS / 4) + c] = W4[i4];
            }
        }
        {
            const float4* __restrict__ E4 = (const float4*)E;
            float4* __restrict__ sA4 = (float4*)sA;
#pragma unroll
            for (int t = 0; t < 2; ++t) {
                const int i4 = tid + t * 256;         // 0..511
                const int r  = row0 + (i4 >> 5);
                const int c  = i4 & 31;
                sA4[i4] = (r < nrows) ? E4[(size_t)r * (D / 4) + c]
                                      : make_float4(0.f, 0.f, 0.f, 0.f);
            }
        }
        __syncthreads();

        float acc0[4] = {0.f, 0.f, 0.f, 0.f};
        float acc1[4] = {0.f, 0.f, 0.f, 0.f};
        const float4* __restrict__ a0  = ((const float4*)sA) + (2 * ty + 0) * (D / 4);
        const float4* __restrict__ a1  = ((const float4*)sA) + (2 * ty + 1) * (D / 4);
        const float4* __restrict__ w4b = (const float4*)sW;

#pragma unroll 4
        for (int k4 = 0; k4 < D / 4; ++k4) {
            const float4 va = a0[k4];
            const float4 vb = a1[k4];
#pragma unroll
            for (int j = 0; j < 4; ++j) {
                const float4 w = w4b[(tx + 32 * j) * (SWS / 4) + k4];
                acc0[j] += va.x * w.x; acc0[j] += va.y * w.y;
                acc0[j] += va.z * w.z; acc0[j] += va.w * w.w;
                acc1[j] += vb.x * w.x; acc1[j] += vb.y * w.y;
                acc1[j] += vb.z * w.z; acc1[j] += vb.w * w.w;
            }
        }

        const int r0 = row0 + 2 * ty;
        if (r0 < nrows) {
#pragma unroll
            for (int j = 0; j < 4; ++j)
                g_Ep[(size_t)r0 * D + tx + 32 * j] = acc0[j];
        }
        if (r0 + 1 < nrows) {
#pragma unroll
            for (int j = 0; j < 4; ++j)
                g_Ep[(size_t)(r0 + 1) * D + tx + 32 * j] = acc1[j];
        }
    } else {
        // ---------------- scan CTA ----------------
        int nb = (bid + 1) >> 2;          // gemm slots strictly below bid
        if (nb > nGemm) nb = nGemm;
        const int sid = bid - nb;
        if (sid >= B) return;

        __shared__ int s_cnt;
        if (tid == 0) s_cnt = 0;
        __syncthreads();

        const int uid = ids[sid];
        const float* __restrict__ row = F + (size_t)uid * (size_t)n_total;
        int*   __restrict__ my_idx = g_idx + (size_t)sid * MAXNZ;
        float* __restrict__ my_w   = g_wv  + (size_t)sid * MAXNZ;

        if (((n_total & 3) == 0) && ((((uintptr_t)row) & 15) == 0)) {
            const float4* __restrict__ row4 = (const float4*)row;
            const int nvec = n_total >> 2;
            for (int i = tid; i < nvec; i += 256) {
                float4 v = row4[i];
                if (v.x != 0.0f) { int p = atomicAdd(&s_cnt, 1); if (p < MAXNZ) { my_idx[p] = 4*i + 0; my_w[p] = v.x; } }
                if (v.y != 0.0f) { int p = atomicAdd(&s_cnt, 1); if (p < MAXNZ) { my_idx[p] = 4*i + 1; my_w[p] = v.y; } }
                if (v.z != 0.0f) { int p = atomicAdd(&s_cnt, 1); if (p < MAXNZ) { my_idx[p] = 4*i + 2; my_w[p] = v.z; } }
                if (v.w != 0.0f) { int p = atomicAdd(&s_cnt, 1); if (p < MAXNZ) { my_idx[p] = 4*i + 3; my_w[p] = v.w; } }
            }
        } else {
            for (int i = tid; i < n_total; i += 256) {
                float v = row[i];
                if (v != 0.0f) { int p = atomicAdd(&s_cnt, 1); if (p < MAXNZ) { my_idx[p] = i; my_w[p] = v; } }
            }
        }
        __syncthreads();
        if (tid == 0) g_cnt[sid] = min(s_cnt, MAXNZ);
    }
}

// ---------------------------------------------------------------------------
// Kernel B: out[b][d] = bias[d] + sum_j w_j * E'[idx_j][d]
// One CTA per batch row, 128 threads; E' and the lists are L2-resident.
// ---------------------------------------------------------------------------
__global__ __launch_bounds__(128) void apply_kernel(
    const float* __restrict__ bias,
    float* __restrict__ out)
{
    const int b = blockIdx.x;
    const int d = threadIdx.x;
    const int cnt = g_cnt[b];
    const int*   __restrict__ idx = g_idx + (size_t)b * MAXNZ;
    const float* __restrict__ w   = g_wv  + (size_t)b * MAXNZ;

    float acc = 0.0f;
    int j = 0;
    for (; j + 8 <= cnt; j += 8) {
        float e0 = g_Ep[(size_t)idx[j+0] * D + d];
        float e1 = g_Ep[(size_t)idx[j+1] * D + d];
        float e2 = g_Ep[(size_t)idx[j+2] * D + d];
        float e3 = g_Ep[(size_t)idx[j+3] * D + d];
        float e4 = g_Ep[(size_t)idx[j+4] * D + d];
        float e5 = g_Ep[(size_t)idx[j+5] * D + d];
        float e6 = g_Ep[(size_t)idx[j+6] * D + d];
        float e7 = g_Ep[(size_t)idx[j+7] * D + d];
        acc += w[j+0] * e0; acc += w[j+1] * e1;
        acc += w[j+2] * e2; acc += w[j+3] * e3;
        acc += w[j+4] * e4; acc += w[j+5] * e5;
        acc += w[j+6] * e6; acc += w[j+7] * e7;
    }
    for (; j < cnt; ++j)
        acc += w[j] * g_Ep[(size_t)idx[j] * D + d];

    out[(size_t)b * D + d] = acc + bias[d];
}

extern "C" void kernel_launch(void* const* d_in, const int* in_sizes, int n_in,
                              void* d_out, int out_size)
{
    const int*   ids  = (const int*)  d_in[0];
    const float* F    = (const float*)d_in[1];
    const float* E    = (const float*)d_in[2];
    const float* W    = (const float*)d_in[3];
    const float* bias = (const float*)d_in[4];
    float* out = (float*)d_out;

    const int B       = in_sizes[0];
    const int nrows   = in_sizes[2] / D;
    const int n_total = in_sizes[1] / nrows;   // F is (nrows, nrows)
    const int nGemm   = (nrows + BM - 1) / BM;

    const int smemA = (D * SWS + BM * D) * (int)sizeof(float);  // 75776 B
    cudaFuncSetAttribute(scan_gemm_kernel, cudaFuncAttributeMaxDynamicSharedMemorySize, smemA);

    scan_gemm_kernel<<<B + nGemm, 256, smemA>>>(ids, F, E, W, n_total, nrows, B, nGemm);
    apply_kernel<<<B, 128>>>(bias, out);
}

// round 8
// speedup vs baseline: 1.2978x; 1.2978x over previous
#include <cuda_runtime.h>
#include <cuda_bf16.h>
#include <cstdint>

#define D 128
#define MAXNZ 512
#define BM 16              // E-rows per GEMM CTA
#define SWS 132            // sW float stride -> conflict-free LDS.128 across d
#define MAXN 10240

__device__ float g_Ep[(size_t)MAXN * D];   // E' = E @ W^T

// ---------------------------------------------------------------------------
// Kernel 1: E'[r][d] = sum_k E[r][k] * W[d][k]
// BM=16 rows/CTA, 256 threads, grid = nrows/16 = 632 -> 3 CTAs/SM.
// W staged in smem (stride-132, conflict-free LDS.128), R=2 register tile.
// ---------------------------------------------------------------------------
__global__ __launch_bounds__(256) void gemm_kernel(
    const float* __restrict__ E,
    const float* __restrict__ W,
    int nrows)
{
    extern __shared__ __align__(16) float smem[];
    float* sW = smem;                 // [128][SWS]
    float* sA = smem + D * SWS;       // [BM][128]

    const int tid  = threadIdx.x;
    const int tx   = tid & 31;
    const int ty   = tid >> 5;
    const int row0 = blockIdx.x * BM;

    {
        const float4* __restrict__ W4 = (const float4*)W;
        float4* __restrict__ sW4 = (float4*)sW;
#pragma unroll
        for (int t = 0; t < 16; ++t) {
            const int i4 = tid + t * 256;     // 0..4095
            const int dd = i4 >> 5;
            const int c  = i4 & 31;
            sW4[dd * (SWS / 4) + c] = W4[i4];
        }
    }
    {
        const float4* __restrict__ E4 = (const float4*)E;
        float4* __restrict__ sA4 = (float4*)sA;
#pragma unroll
        for (int t = 0; t < 2; ++t) {
            const int i4 = tid + t * 256;     // 0..511
            const int r  = row0 + (i4 >> 5);
            const int c  = i4 & 31;
            sA4[i4] = (r < nrows) ? E4[(size_t)r * (D / 4) + c]
                                  : make_float4(0.f, 0.f, 0.f, 0.f);
        }
    }
    __syncthreads();

    float acc0[4] = {0.f, 0.f, 0.f, 0.f};
    float acc1[4] = {0.f, 0.f, 0.f, 0.f};
    const float4* __restrict__ a0  = ((const float4*)sA) + (2 * ty + 0) * (D / 4);
    const float4* __restrict__ a1  = ((const float4*)sA) + (2 * ty + 1) * (D / 4);
    const float4* __restrict__ w4b = (const float4*)sW;

#pragma unroll 4
    for (int k4 = 0; k4 < D / 4; ++k4) {
        const float4 va = a0[k4];
        const float4 vb = a1[k4];
#pragma unroll
        for (int j = 0; j < 4; ++j) {
            const float4 w = w4b[(tx + 32 * j) * (SWS / 4) + k4];
            acc0[j] += va.x * w.x; acc0[j] += va.y * w.y;
            acc0[j] += va.z * w.z; acc0[j] += va.w * w.w;
            acc1[j] += vb.x * w.x; acc1[j] += vb.y * w.y;
            acc1[j] += vb.z * w.z; acc1[j] += vb.w * w.w;
        }
    }

    const int r0 = row0 + 2 * ty;
    if (r0 < nrows) {
#pragma unroll
        for (int j = 0; j < 4; ++j)
            g_Ep[(size_t)r0 * D + tx + 32 * j] = acc0[j];
    }
    if (r0 + 1 < nrows) {
#pragma unroll
        for (int j = 0; j < 4; ++j)
            g_Ep[(size_t)(r0 + 1) * D + tx + 32 * j] = acc1[j];
    }
}

// ---------------------------------------------------------------------------
// Kernel 2: out[b][d] = bias[d] + sum_n F[uid_b][n] * E'[n][d]
// R3-proven structure: one CTA / batch row, 128 threads, smem-resident
// nonzero lists; small smem -> 16 CTAs/SM, scan keeps full DRAM MLP.
// ---------------------------------------------------------------------------
__global__ __launch_bounds__(128) void agg_kernel(
    const int* __restrict__ ids,
    const float* __restrict__ F,
    const float* __restrict__ bias,
    int n_total,
    float* __restrict__ out)
{
    __shared__ int   s_idx[MAXNZ];
    __shared__ float s_w[MAXNZ];
    __shared__ int   s_cnt;

    const int tid = threadIdx.x;
    if (tid == 0) s_cnt = 0;
    __syncthreads();

    const int uid = ids[blockIdx.x];
    const float* __restrict__ row = F + (size_t)uid * (size_t)n_total;

    if (((n_total & 3) == 0) && ((((uintptr_t)row) & 15) == 0)) {
        const float4* __restrict__ row4 = (const float4*)row;
        const int nvec = n_total >> 2;
        for (int i = tid; i < nvec; i += 128) {
            float4 v = row4[i];
            if (v.x != 0.0f) { int p = atomicAdd(&s_cnt, 1); if (p < MAXNZ) { s_idx[p] = 4*i + 0; s_w[p] = v.x; } }
            if (v.y != 0.0f) { int p = atomicAdd(&s_cnt, 1); if (p < MAXNZ) { s_idx[p] = 4*i + 1; s_w[p] = v.y; } }
            if (v.z != 0.0f) { int p = atomicAdd(&s_cnt, 1); if (p < MAXNZ) { s_idx[p] = 4*i + 2; s_w[p] = v.z; } }
            if (v.w != 0.0f) { int p = atomicAdd(&s_cnt, 1); if (p < MAXNZ) { s_idx[p] = 4*i + 3; s_w[p] = v.w; } }
        }
    } else {
        for (int i = tid; i < n_total; i += 128) {
            float v = row[i];
            if (v != 0.0f) { int p = atomicAdd(&s_cnt, 1); if (p < MAXNZ) { s_idx[p] = i; s_w[p] = v; } }
        }
    }
    __syncthreads();

    const int cnt = min(s_cnt, MAXNZ);
    const int d = tid;
    float acc = 0.0f;

    int j = 0;
    for (; j + 4 <= cnt; j += 4) {
        const float w0 = s_w[j + 0], w1 = s_w[j + 1], w2 = s_w[j + 2], w3 = s_w[j + 3];
        const float e0 = g_Ep[(size_t)s_idx[j + 0] * D + d];
        const float e1 = g_Ep[(size_t)s_idx[j + 1] * D + d];
        const float e2 = g_Ep[(size_t)s_idx[j + 2] * D + d];
        const float e3 = g_Ep[(size_t)s_idx[j + 3] * D + d];
        acc += w0 * e0;
        acc += w1 * e1;
        acc += w2 * e2;
        acc += w3 * e3;
    }
    for (; j < cnt; ++j)
        acc += s_w[j] * g_Ep[(size_t)s_idx[j] * D + d];

    out[(size_t)blockIdx.x * D + d] = acc + bias[d];
}

extern "C" void kernel_launch(void* const* d_in, const int* in_sizes, int n_in,
                              void* d_out, int out_size)
{
    const int*   ids  = (const int*)  d_in[0];
    const float* F    = (const float*)d_in[1];
    const float* E    = (const float*)d_in[2];
    const float* W    = (const float*)d_in[3];
    const float* bias = (const float*)d_in[4];
    float* out = (float*)d_out;

    const int B       = in_sizes[0];
    const int nrows   = in_sizes[2] / D;
    const int n_total = in_sizes[1] / nrows;   // F is (n_total, n_total), == nrows

    const int smemG = (D * SWS + BM * D) * (int)sizeof(float);  // 75776 B
    cudaFuncSetAttribute(gemm_kernel, cudaFuncAttributeMaxDynamicSharedMemorySize, smemG);

    gemm_kernel<<<(nrows + BM - 1) / BM, 256, smemG>>>(E, W, nrows);
    agg_kernel<<<B, 128>>>(ids, F, bias, n_total, out);
}

// round 9
// speedup vs baseline: 2.1102x; 1.6260x over previous
#include <cuda_runtime.h>
#include <cuda_bf16.h>
#include <cstdint>

#define D 128
#define MAXNZ 512
#define BM 16              // batch rows per lin CTA
#define DN 32              // output cols per lin CTA
#define SWS 132            // smem W row stride (floats) -> conflict-free LDS.128
#define MAXB 4096

__device__ float g_agg[(size_t)MAXB * D];

// ---------------------------------------------------------------------------
// Kernel 1 (R3-proven, ~14.5us): scan F[uid] + sparse aggregate vs E.
// ---------------------------------------------------------------------------
__global__ __launch_bounds__(128) void agg_kernel(
    const int* __restrict__ ids,
    const float* __restrict__ F,
    const float* __restrict__ E,
    int n_total,
    float* __restrict__ agg)
{
    __shared__ int   s_idx[MAXNZ];
    __shared__ float s_w[MAXNZ];
    __shared__ int   s_cnt;

    const int tid = threadIdx.x;
    if (tid == 0) s_cnt = 0;
    __syncthreads();

    const int uid = ids[blockIdx.x];
    const float* __restrict__ row = F + (size_t)uid * (size_t)n_total;

    if (((n_total & 3) == 0) && ((((uintptr_t)row) & 15) == 0)) {
        const float4* __restrict__ row4 = (const float4*)row;
        const int nvec = n_total >> 2;
        for (int i = tid; i < nvec; i += 128) {
            float4 v = row4[i];
            if (v.x != 0.0f) { int p = atomicAdd(&s_cnt, 1); if (p < MAXNZ) { s_idx[p] = 4*i + 0; s_w[p] = v.x; } }
            if (v.y != 0.0f) { int p = atomicAdd(&s_cnt, 1); if (p < MAXNZ) { s_idx[p] = 4*i + 1; s_w[p] = v.y; } }
            if (v.z != 0.0f) { int p = atomicAdd(&s_cnt, 1); if (p < MAXNZ) { s_idx[p] = 4*i + 2; s_w[p] = v.z; } }
            if (v.w != 0.0f) { int p = atomicAdd(&s_cnt, 1); if (p < MAXNZ) { s_idx[p] = 4*i + 3; s_w[p] = v.w; } }
        }
    } else {
        for (int i = tid; i < n_total; i += 128) {
            float v = row[i];
            if (v != 0.0f) { int p = atomicAdd(&s_cnt, 1); if (p < MAXNZ) { s_idx[p] = i; s_w[p] = v; } }
        }
    }
    __syncthreads();

    const int cnt = min(s_cnt, MAXNZ);
    const int d = tid;
    float acc = 0.0f;

    int j = 0;
    for (; j + 4 <= cnt; j += 4) {
        const float w0 = s_w[j + 0], w1 = s_w[j + 1], w2 = s_w[j + 2], w3 = s_w[j + 3];
        const float e0 = E[(size_t)s_idx[j + 0] * D + d];
        const float e1 = E[(size_t)s_idx[j + 1] * D + d];
        const float e2 = E[(size_t)s_idx[j + 2] * D + d];
        const float e3 = E[(size_t)s_idx[j + 3] * D + d];
        acc += w0 * e0;
        acc += w1 * e1;
        acc += w2 * e2;
        acc += w3 * e3;
    }
    for (; j < cnt; ++j)
        acc += s_w[j] * E[(size_t)s_idx[j] * D + d];

    agg[(size_t)blockIdx.x * D + d] = acc;
}

// ---------------------------------------------------------------------------
// Kernel 2: out[b][d] = bias[d] + sum_k agg[b][k] * W[d][k]
// d-split tiles: CTA = 16 rows x 32 cols, grid = (B/16, 4), 128 threads.
// Stages only W[d0:d0+32][0:128] = 16KB (+8KB agg) -> 3-4 CTAs/SM.
// Thread (tx,ty): col d0+tx, rows 4ty..4ty+3 (R=4).
// Per k4-iter/warp: 1 conflict-free LDS.128 (W) + 4 broadcast LDS.128 (agg)
//   -> 16 FMA-instr.  FMA:crossbar ratio ~2:1.
// ---------------------------------------------------------------------------
__global__ __launch_bounds__(128) void lin_kernel(
    const float* __restrict__ agg,
    const float* __restrict__ W,
    const float* __restrict__ bias,
    float* __restrict__ out,
    int B)
{
    __shared__ __align__(16) float sW[DN * SWS];   // [32][132]
    __shared__ __align__(16) float sA[BM * D];     // [16][128]

    const int tid = threadIdx.x;
    const int tx  = tid & 31;          // col within tile
    const int ty  = tid >> 5;          // 0..3 -> row quad
    const int row0 = blockIdx.x * BM;
    const int d0   = blockIdx.y * DN;

    // stage W tile: 32 rows x 32 float4 = 1024 float4, 8 per thread
    {
        const float4* __restrict__ W4 = (const float4*)W;
        float4* __restrict__ sW4 = (float4*)sW;
#pragma unroll
        for (int t = 0; t < 8; ++t) {
            const int i4  = tid + t * 128;     // 0..1023
            const int c   = i4 >> 5;           // W row within tile
            const int k4c = i4 & 31;
            sW4[c * (SWS / 4) + k4c] = W4[(size_t)(d0 + c) * (D / 4) + k4c];
        }
    }
    // stage agg tile: 512 float4, 4 per thread
    {
        const float4* __restrict__ A4 = (const float4*)(agg + (size_t)row0 * D);
        float4* __restrict__ sA4 = (float4*)sA;
#pragma unroll
        for (int t = 0; t < 4; ++t) {
            const int i4 = tid + t * 128;
            sA4[i4] = A4[i4];
        }
    }
    __syncthreads();

    float acc[4] = {0.f, 0.f, 0.f, 0.f};
    const float4* __restrict__ a4 = (const float4*)sA;
    const float4* __restrict__ w4 = ((const float4*)sW) + tx * (SWS / 4);

#pragma unroll 8
    for (int k4 = 0; k4 < D / 4; ++k4) {
        const float4 w = w4[k4];                         // conflict-free
#pragma unroll
        for (int r = 0; r < 4; ++r) {
            const float4 a = a4[(4 * ty + r) * (D / 4) + k4];  // broadcast
            acc[r] += a.x * w.x;
            acc[r] += a.y * w.y;
            acc[r] += a.z * w.z;
            acc[r] += a.w * w.w;
        }
    }

    const float b = bias[d0 + tx];
#pragma unroll
    for (int r = 0; r < 4; ++r) {
        const int rr = row0 + 4 * ty + r;
        if (rr < B)
            out[(size_t)rr * D + d0 + tx] = acc[r] + b;
    }
}

extern "C" void kernel_launch(void* const* d_in, const int* in_sizes, int n_in,
                              void* d_out, int out_size)
{
    const int*   ids  = (const int*)  d_in[0];
    const float* F    = (const float*)d_in[1];
    const float* E    = (const float*)d_in[2];
    const float* W    = (const float*)d_in[3];
    const float* bias = (const float*)d_in[4];
    float* out = (float*)d_out;

    const int B       = in_sizes[0];
    const int n_total = in_sizes[2] / D;

    float* agg;
    cudaGetSymbolAddress((void**)&agg, g_agg);

    agg_kernel<<<B, 128>>>(ids, F, E, n_total, agg);

    dim3 grid2((B + BM - 1) / BM, D / DN);
    lin_kernel<<<grid2, 128>>>(agg, W, bias, out, B);
}